// round 7
// baseline (speedup 1.0000x reference)
#include <cuda_runtime.h>
#include <cstddef>

typedef unsigned long long u64;

// Problem constants
#define NB   1024
#define NT   1024
#define KQ   15
#define KT   20
#define NDOF 7

// Output layout offsets (fp32 elements), total = 38,827,009
static constexpr size_t OFF_MODEL       = 0;
static constexpr size_t OFF_QDOT_LOSS   = 1;
static constexpr size_t OFF_QDDOT_LOSS  = 1 + 7168;
static constexpr size_t OFF_QDDDOT_LOSS = 1 + 2 * 7168;
static constexpr size_t OFF_TORQUE_LOSS = 1 + 3 * 7168;
static constexpr size_t OFF_Q           = 1 + 4 * 7168;           // 28673 (== 1 mod 4)
static constexpr size_t QTD             = (size_t)NB * NT * NDOF; // 7,340,032
static constexpr size_t OFF_QDOT        = OFF_Q + QTD;
static constexpr size_t OFF_QDDOT       = OFF_Q + 2 * QTD;
static constexpr size_t OFF_QDDDOT      = OFF_Q + 3 * QTD;
static constexpr size_t OFF_TORQUE      = OFF_Q + 4 * QTD;
static constexpr size_t OFF_T           = OFF_Q + 5 * QTD;
static constexpr size_t OFF_TCUM        = OFF_T + NB;
static constexpr size_t OFF_DT          = OFF_TCUM + (size_t)NB * NT;

// Scratch: per-(b,t) time-spline coefficients {a=dtau, ddtau, dddtau, dt}
__device__ float4 g_coeff[(size_t)NB * NT];   // 16 MB static device array

// ---- packed f32x2 helpers -------------------------------------------------
#define PACK2(out, lo, hi) \
    asm("mov.b64 %0, {%1, %2};" : "=l"(out) : "r"(__float_as_uint(lo)), "r"(__float_as_uint(hi)))
#define UNPACK2(lo, hi, in) do { unsigned int _ulo, _uhi; \
    asm("mov.b64 {%0, %1}, %2;" : "=r"(_ulo), "=r"(_uhi) : "l"(in)); \
    lo = __uint_as_float(_ulo); hi = __uint_as_float(_uhi); } while (0)
#define FMA2(d, a, b, c) asm("fma.rn.f32x2 %0, %1, %2, %3;" : "=l"(d) : "l"(a), "l"(b), "l"(c))
#define MUL2(d, a, b)    asm("mul.rn.f32x2 %0, %1, %2;"     : "=l"(d) : "l"(a), "l"(b))

__device__ __forceinline__ float huber_relu_dt(float v, float lim, float dt) {
    // huber(relu(|v| - lim), delta=1) * dt, branchless:
    // r = relu(|v|-lim); m = min(r,1); h = (r - 0.5m)*m
    float r = fmaxf(fabsf(v) - lim, 0.0f);
    float m = fminf(r, 1.0f);
    return (r - 0.5f * m) * m * dt;
}

// ---------------------------------------------------------------------------
// Kernel A: time-spline coefficients. Grid (32 t-tiles, 32 b-tiles), 1024 thr.
// ---------------------------------------------------------------------------
__global__ __launch_bounds__(1024)
void coeff_kernel(const float* __restrict__ t_cps,
                  const float* __restrict__ Nt,  const float* __restrict__ dNt,
                  const float* __restrict__ ddNt,
                  float* __restrict__ out)
{
    __shared__ float sB[3][KT][32];   // [plane][k][t-local]
    __shared__ float sT[32][KT];      // [b-local][k]

    const int tid = threadIdx.x;
    const int t0  = blockIdx.x * 32;
    const int b0  = blockIdx.y * 32;

    {
        const float* src[3] = {Nt, dNt, ddNt};
#pragma unroll
        for (int p = 0; p < 3; p++)
            for (int idx = tid; idx < 32 * KT; idx += 1024) {
                int lt = idx / KT, k = idx % KT;
                sB[p][k][lt] = src[p][(t0 + lt) * KT + k];
            }
    }
    for (int idx = tid; idx < 32 * KT; idx += 1024) {
        int bl = idx / KT, k = idx % KT;
        sT[bl][k] = t_cps[(b0 + bl) * KT + k];
    }
    __syncthreads();

    const int tx = tid & 31;
    const int ty = tid >> 5;
    const int b  = b0 + ty;
    const int t  = t0 + tx;

    float a = 0.0f, dd = 0.0f, ddd = 0.0f;
#pragma unroll
    for (int k = 0; k < KT; k++) {
        float c = sT[ty][k];
        a   = fmaf(sB[0][k][tx], c, a);
        dd  = fmaf(sB[1][k][tx], c, dd);
        ddd = fmaf(sB[2][k][tx], c, ddd);
    }
    const float dt = 1.0f / (a * (float)NT);

    g_coeff[(size_t)b * NT + t] = make_float4(a, dd, ddd, dt);
    out[OFF_DT + (size_t)b * NT + t] = dt;
}

// ---------------------------------------------------------------------------
// Kernel B: per-batch inclusive cumsum of dt -> t_cumsum, t. Block = batch.
// ---------------------------------------------------------------------------
__global__ __launch_bounds__(1024)
void cumsum_kernel(float* __restrict__ out)
{
    __shared__ float s_w[32];
    const int t    = threadIdx.x;
    const int lane = t & 31;
    const int wid  = t >> 5;
    const int b    = blockIdx.x;

    float v = out[OFF_DT + (size_t)b * NT + t];
#pragma unroll
    for (int off = 1; off < 32; off <<= 1) {
        float u = __shfl_up_sync(0xffffffffu, v, off);
        if (lane >= off) v += u;
    }
    if (lane == 31) s_w[wid] = v;
    __syncthreads();
    if (wid == 0) {
        float wv = s_w[lane];
#pragma unroll
        for (int off = 1; off < 32; off <<= 1) {
            float u = __shfl_up_sync(0xffffffffu, wv, off);
            if (lane >= off) wv += u;
        }
        s_w[lane] = wv;
    }
    __syncthreads();
    float c = v + (wid > 0 ? s_w[wid - 1] : 0.0f);

    out[OFF_TCUM + (size_t)b * NT + t] = c;
    if (t == NT - 1) out[OFF_T + b] = c;
}

// ---------------------------------------------------------------------------
// Flush a staged 224-float chunk (data at buf[1..224]) to g (g%4 floats == 1):
// 55x STG.128 body + 4 scalar edges.
// ---------------------------------------------------------------------------
__device__ __forceinline__ void flush_chunk(float* __restrict__ g,
                                            const float* __restrict__ buf,
                                            int lane)
{
    float4 x0 = *(const float4*)(buf + 4 * (lane + 1));
    *(float4*)(g + 4 * (lane + 1) - 1) = x0;
    if (lane < 23) {
        float4 x1 = *(const float4*)(buf + 4 * (lane + 33));
        *(float4*)(g + 4 * (lane + 33) - 1) = x1;
    }
    if (lane < 3)       g[lane] = buf[lane + 1];
    else if (lane == 3) g[223]  = buf[224];
}

// ---------------------------------------------------------------------------
// Kernel C: main streaming kernel (packed f32x2 over the two t-points).
// Tile: T_TILE=64 x B_TILE=8 batches, 256 threads (warp = batch).
// ---------------------------------------------------------------------------
#define T_TILE 64
#define B_TILE 8
#define THR    256

__global__ __launch_bounds__(THR)
void main_kernel(const float* __restrict__ q_cps,
                 const float* __restrict__ N,   const float* __restrict__ dN,
                 const float* __restrict__ ddN, const float* __restrict__ dddN,
                 const float* __restrict__ Ldot, const float* __restrict__ Lddot,
                 const float* __restrict__ Ldddot,
                 float* __restrict__ out)
{
    __shared__ float4 s_qb[T_TILE][17];          // [lt][k] = {N,dN,ddN,dddN}, pad 17
    __shared__ u64    s_qcd[B_TILE][KQ][8];      // duplicated pairs (c,c); slot 7 unused
    __shared__ float  s_lims[24];
    __shared__ float  s_stage[B_TILE][4][240];   // per-warp, 4 streams, one i at a time
    __shared__ float  s_model[B_TILE];

    const int tid = threadIdx.x;
    const int t0  = blockIdx.x * T_TILE;
    const int b0  = blockIdx.y * B_TILE;

    {
        const float* qa[4] = {N, dN, ddN, dddN};
#pragma unroll
        for (int a = 0; a < 4; a++) {
            const float* src = qa[a];
            for (int idx = tid; idx < T_TILE * KQ; idx += THR) {
                int lt = idx / KQ, k = idx % KQ;
                ((float*)&s_qb[lt][k])[a] = src[(t0 + lt) * KQ + k];
            }
        }
    }
    for (int idx = tid; idx < B_TILE * KQ * NDOF; idx += THR) {
        int w = idx / (KQ * NDOF), r = idx % (KQ * NDOF);
        float c = q_cps[(size_t)b0 * KQ * NDOF + idx];
        u64 p; PACK2(p, c, c);
        s_qcd[w][r / NDOF][r % NDOF] = p;
    }
    if (tid < 7) {
        s_lims[tid]      = Ldot[tid];
        s_lims[7 + tid]  = Lddot[tid];
        s_lims[14 + tid] = Ldddot[tid];
    }
    __syncthreads();

    const int lane = tid & 31;
    const int w    = tid >> 5;   // local batch 0..7
    const int b    = b0 + w;

    // time-spline coeff pairs for t-points (t0+lane, t0+lane+32)
    const float4 cf0 = g_coeff[(size_t)b * NT + t0 + lane];
    const float4 cf1 = g_coeff[(size_t)b * NT + t0 + lane + 32];
    u64 ap, ddp, dddp;
    PACK2(ap,   cf0.x, cf1.x);
    PACK2(ddp,  cf0.y, cf1.y);
    PACK2(dddp, cf0.z, cf1.z);
    u64 a2p; MUL2(a2p, ap, ap);
    u64 a3p; MUL2(a3p, a2p, ap);
    u64 c1p; MUL2(c1p, ddp, ap);                       // ddtau * a
    u64 c2p; { u64 t; MUL2(t, ddp, a2p); u64 th; PACK2(th, 3.0f, 3.0f); MUL2(c2p, th, t); } // 3*ddtau*a2
    u64 c3p; { u64 t; MUL2(t, ddp, ddp); u64 t2; MUL2(t2, t, ap); FMA2(c3p, a2p, dddp, t2); } // a2*dddtau + ddtau^2*a
    const float dth[2] = {cf0.w, cf1.w};

    // packed spline accumulation over k
    u64 q[7]    = {0,0,0,0,0,0,0};
    u64 qd[7]   = {0,0,0,0,0,0,0};
    u64 qdd[7]  = {0,0,0,0,0,0,0};
    u64 qddd[7] = {0,0,0,0,0,0,0};
#pragma unroll
    for (int k = 0; k < KQ; k++) {
        float4 b0v = s_qb[lane][k];
        float4 b1v = s_qb[lane + 32][k];
        u64 nbx, nby, nbz, nbw;
        PACK2(nbx, b0v.x, b1v.x);
        PACK2(nby, b0v.y, b1v.y);
        PACK2(nbz, b0v.z, b1v.z);
        PACK2(nbw, b0v.w, b1v.w);
#pragma unroll
        for (int d = 0; d < 7; d++) {
            u64 cs = s_qcd[w][k][d];  // broadcast LDS.64
            FMA2(q[d],    nbx, cs, q[d]);
            FMA2(qd[d],   nby, cs, qd[d]);
            FMA2(qdd[d],  nbz, cs, qdd[d]);
            FMA2(qddd[d], nbw, cs, qddd[d]);
        }
    }

    float accd[7]   = {0,0,0,0,0,0,0};
    float accdd[7]  = {0,0,0,0,0,0,0};
    float accddd[7] = {0,0,0,0,0,0,0};

    float* st0 = s_stage[w][0];
    float* st1 = s_stage[w][1];
    float* st2 = s_stage[w][2];
    float* st3 = s_stage[w][3];

#pragma unroll
    for (int i = 0; i < 2; i++) {
        const float dt = dth[i];
#pragma unroll
        for (int d = 0; d < 7; d++) {
            u64 v1; MUL2(v1, qd[d], ap);
            u64 tA; MUL2(tA, qd[d], c1p);
            u64 v2; FMA2(v2, qdd[d], a2p, tA);
            u64 tB; MUL2(tB, qd[d], c3p);
            u64 tC; FMA2(tC, qdd[d], c2p, tB);
            u64 v3; FMA2(v3, qddd[d], a3p, tC);

            float qlo, qhi, w1l, w1h, w2l, w2h, w3l, w3h;
            UNPACK2(qlo, qhi, q[d]);
            UNPACK2(w1l, w1h, v1);
            UNPACK2(w2l, w2h, v2);
            UNPACK2(w3l, w3h, v3);
            float qv = (i == 0) ? qlo : qhi;
            float x1 = (i == 0) ? w1l : w1h;
            float x2 = (i == 0) ? w2l : w2h;
            float x3 = (i == 0) ? w3l : w3h;

            st0[1 + 7 * lane + d] = qv;   // conflict-free (gcd(7,32)=1)
            st1[1 + 7 * lane + d] = x1;
            st2[1 + 7 * lane + d] = x2;
            st3[1 + 7 * lane + d] = x3;

            accd[d]   += huber_relu_dt(x1, s_lims[d],      dt);
            accdd[d]  += huber_relu_dt(x2, s_lims[7 + d],  dt);
            accddd[d] += huber_relu_dt(x3, s_lims[14 + d], dt);
        }
        __syncwarp();
        const size_t chunk = ((size_t)b * NT + t0 + 32 * i) * NDOF; // multiple of 224
        flush_chunk(out + OFF_Q      + chunk, st0, lane);
        flush_chunk(out + OFF_QDOT   + chunk, st1, lane);
        flush_chunk(out + OFF_QDDOT  + chunk, st2, lane);
        flush_chunk(out + OFF_QDDDOT + chunk, st3, lane);
        __syncwarp();
    }

    // warp-reduce the 21 loss accumulators (all lanes same b)
#pragma unroll
    for (int d = 0; d < 7; d++) {
#pragma unroll
        for (int off = 16; off; off >>= 1) {
            accd[d]   += __shfl_xor_sync(0xffffffffu, accd[d],   off);
            accdd[d]  += __shfl_xor_sync(0xffffffffu, accdd[d],  off);
            accddd[d] += __shfl_xor_sync(0xffffffffu, accddd[d], off);
        }
    }
    if (lane == 0) {
        float tot = 0.0f;
#pragma unroll
        for (int d = 0; d < 7; d++) {
            atomicAdd(&out[OFF_QDOT_LOSS   + (size_t)b * NDOF + d], accd[d]);
            atomicAdd(&out[OFF_QDDOT_LOSS  + (size_t)b * NDOF + d], accdd[d]);
            atomicAdd(&out[OFF_QDDDOT_LOSS + (size_t)b * NDOF + d], accddd[d]);
            tot += accd[d] + accdd[d] + accddd[d];
        }
        s_model[w] = tot;
    }
    __syncthreads();
    if (tid == 0) {
        float m = 0.0f;
#pragma unroll
        for (int ww = 0; ww < B_TILE; ww++) m += s_model[ww];
        atomicAdd(&out[OFF_MODEL], m);   // fused finalize
    }
}

// ---------------------------------------------------------------------------
extern "C" void kernel_launch(void* const* d_in, const int* in_sizes, int n_in,
                              void* d_out, int out_size)
{
    const float* q_cps  = (const float*)d_in[0];
    const float* t_cps  = (const float*)d_in[1];
    const float* N      = (const float*)d_in[2];
    const float* dN     = (const float*)d_in[3];
    const float* ddN    = (const float*)d_in[4];
    const float* dddN   = (const float*)d_in[5];
    const float* Nt     = (const float*)d_in[6];
    const float* dNt    = (const float*)d_in[7];
    const float* ddNt   = (const float*)d_in[8];
    const float* Ldot   = (const float*)d_in[9];
    const float* Lddot  = (const float*)d_in[10];
    const float* Ldddot = (const float*)d_in[11];
    // d_in[12] = torque_limits (unused: torque == 0 -> torque_loss == 0)

    float* out = (float*)d_out;

    // zero model_loss + all four loss regions, and the torque output (all zeros)
    cudaMemsetAsync(out, 0, (size_t)OFF_Q * sizeof(float), 0);
    cudaMemsetAsync(out + OFF_TORQUE, 0, QTD * sizeof(float), 0);

    dim3 cgrid(NT / 32, NB / 32);                 // (32, 32)
    coeff_kernel<<<cgrid, 1024>>>(t_cps, Nt, dNt, ddNt, out);

    cumsum_kernel<<<NB, 1024>>>(out);

    dim3 grid(NT / T_TILE, NB / B_TILE);          // (16, 128)
    main_kernel<<<grid, THR>>>(q_cps, N, dN, ddN, dddN,
                               Ldot, Lddot, Ldddot, out);
}

// round 8
// speedup vs baseline: 1.1030x; 1.1030x over previous
#include <cuda_runtime.h>
#include <cstddef>

typedef unsigned long long u64;

// Problem constants
#define NB   1024
#define NT   1024
#define KQ   15
#define KT   20
#define NDOF 7

// Output layout offsets (fp32 elements), total = 38,827,009
static constexpr size_t OFF_MODEL       = 0;
static constexpr size_t OFF_QDOT_LOSS   = 1;
static constexpr size_t OFF_QDDOT_LOSS  = 1 + 7168;
static constexpr size_t OFF_QDDDOT_LOSS = 1 + 2 * 7168;
static constexpr size_t OFF_TORQUE_LOSS = 1 + 3 * 7168;
static constexpr size_t OFF_Q           = 1 + 4 * 7168;           // 28673 (== 1 mod 4)
static constexpr size_t QTD             = (size_t)NB * NT * NDOF; // 7,340,032
static constexpr size_t OFF_QDOT        = OFF_Q + QTD;
static constexpr size_t OFF_QDDOT       = OFF_Q + 2 * QTD;
static constexpr size_t OFF_QDDDOT      = OFF_Q + 3 * QTD;
static constexpr size_t OFF_TORQUE      = OFF_Q + 4 * QTD;
static constexpr size_t OFF_T           = OFF_Q + 5 * QTD;
static constexpr size_t OFF_TCUM        = OFF_T + NB;
static constexpr size_t OFF_DT          = OFF_TCUM + (size_t)NB * NT;

// ---- packed f32x2 helpers -------------------------------------------------
#define PACK2(out, lo, hi) \
    asm("mov.b64 %0, {%1, %2};" : "=l"(out) : "r"(__float_as_uint(lo)), "r"(__float_as_uint(hi)))
#define UNPACK2(lo, hi, in) do { unsigned int _ulo, _uhi; \
    asm("mov.b64 {%0, %1}, %2;" : "=r"(_ulo), "=r"(_uhi) : "l"(in)); \
    lo = __uint_as_float(_ulo); hi = __uint_as_float(_uhi); } while (0)
#define FMA2(d, a, b, c) asm("fma.rn.f32x2 %0, %1, %2, %3;" : "=l"(d) : "l"(a), "l"(b), "l"(c))
#define MUL2(d, a, b)    asm("mul.rn.f32x2 %0, %1, %2;"     : "=l"(d) : "l"(a), "l"(b))

__device__ __forceinline__ float huber_relu_dt(float v, float lim, float dt) {
    // huber(relu(|v| - lim), delta=1) * dt, branchless
    float r = fmaxf(fabsf(v) - lim, 0.0f);
    float m = fminf(r, 1.0f);
    return (r - 0.5f * m) * m * dt;
}

// ---------------------------------------------------------------------------
// Kernel A: dt stream only. Grid (32 t-tiles of 32, 8 b-tiles of 128), 1024 thr.
// Conflict-free smem layouts: sNt[k][lt] (lt fastest), sT[bl][21-pad].
// ---------------------------------------------------------------------------
__global__ __launch_bounds__(1024)
void dt_kernel(const float* __restrict__ t_cps,
               const float* __restrict__ Nt,
               float* __restrict__ out)
{
    __shared__ float sNt[KT][32];    // [k][t-local]
    __shared__ float sT[128][21];    // [b-local][k], pad 21

    const int tid = threadIdx.x;
    const int t0  = blockIdx.x * 32;
    const int b0  = blockIdx.y * 128;

    if (tid < 32 * KT) {
        int k = tid / 32, lt = tid % 32;              // lt fastest -> STS conflict-free
        sNt[k][lt] = Nt[(t0 + lt) * KT + k];
    }
    for (int idx = tid; idx < 128 * KT; idx += 1024) {
        int bl = idx / KT, k = idx % KT;              // coalesced LDG; pad-21 STS conflict-free
        sT[bl][k] = t_cps[(b0 + bl) * KT + k];
    }
    __syncthreads();

    const int tx = tid & 31;
    const int ty = tid >> 5;
#pragma unroll
    for (int j = 0; j < 4; j++) {
        const int bl = ty + 32 * j;
        float a = 0.0f;
#pragma unroll
        for (int k = 0; k < KT; k++)
            a = fmaf(sNt[k][tx], sT[bl][k], a);       // lane-indexed + broadcast: conflict-free
        out[OFF_DT + (size_t)(b0 + bl) * NT + t0 + tx] = 1.0f / (a * (float)NT);
    }
}

// ---------------------------------------------------------------------------
// Kernel B: per-batch inclusive cumsum of dt -> t_cumsum, t. Block = batch.
// ---------------------------------------------------------------------------
__global__ __launch_bounds__(1024)
void cumsum_kernel(float* __restrict__ out)
{
    __shared__ float s_w[32];
    const int t    = threadIdx.x;
    const int lane = t & 31;
    const int wid  = t >> 5;
    const int b    = blockIdx.x;

    float v = out[OFF_DT + (size_t)b * NT + t];
#pragma unroll
    for (int off = 1; off < 32; off <<= 1) {
        float u = __shfl_up_sync(0xffffffffu, v, off);
        if (lane >= off) v += u;
    }
    if (lane == 31) s_w[wid] = v;
    __syncthreads();
    if (wid == 0) {
        float wv = s_w[lane];
#pragma unroll
        for (int off = 1; off < 32; off <<= 1) {
            float u = __shfl_up_sync(0xffffffffu, wv, off);
            if (lane >= off) wv += u;
        }
        s_w[lane] = wv;
    }
    __syncthreads();
    float c = v + (wid > 0 ? s_w[wid - 1] : 0.0f);

    out[OFF_TCUM + (size_t)b * NT + t] = c;
    if (t == NT - 1) out[OFF_T + b] = c;
}

// ---------------------------------------------------------------------------
// Flush a staged 224-float chunk (data at buf[1..224]) to g (g%4 floats == 1):
// 55x STG.128 body + 4 scalar edges.
// ---------------------------------------------------------------------------
__device__ __forceinline__ void flush_chunk(float* __restrict__ g,
                                            const float* __restrict__ buf,
                                            int lane)
{
    float4 x0 = *(const float4*)(buf + 4 * (lane + 1));
    *(float4*)(g + 4 * (lane + 1) - 1) = x0;
    if (lane < 23) {
        float4 x1 = *(const float4*)(buf + 4 * (lane + 33));
        *(float4*)(g + 4 * (lane + 33) - 1) = x1;
    }
    if (lane < 3)       g[lane] = buf[lane + 1];
    else if (lane == 3) g[223]  = buf[224];
}

// ---------------------------------------------------------------------------
// Kernel C: main streaming kernel (packed f32x2 over the two t-points),
// time-spline fused, packed-pair basis layouts, per-stream staging.
// Tile: T_TILE=64 x B_TILE=8 batches, 256 threads (warp = batch).
// ---------------------------------------------------------------------------
#define T_TILE 64
#define B_TILE 8
#define THR    256

__global__ __launch_bounds__(THR, 3)
void main_kernel(const float* __restrict__ q_cps, const float* __restrict__ t_cps,
                 const float* __restrict__ N,   const float* __restrict__ dN,
                 const float* __restrict__ ddN, const float* __restrict__ dddN,
                 const float* __restrict__ Nt,  const float* __restrict__ dNt,
                 const float* __restrict__ ddNt,
                 const float* __restrict__ Ldot, const float* __restrict__ Lddot,
                 const float* __restrict__ Ldddot,
                 float* __restrict__ out)
{
    __shared__ float2 s_qbp[4][KQ][32];     // [plane][k][lt] = (basis(t0+lt), basis(t0+lt+32))
    __shared__ float2 s_tbp[3][KT][32];     // time-spline pairs, same shape
    __shared__ u64    s_qcd[B_TILE][KQ][8]; // duplicated q_cps pairs (c,c); slot 7 unused
    __shared__ u64    s_tcd[B_TILE][KT];    // duplicated t_cps pairs
    __shared__ float  s_lims[24];
    __shared__ float  s_stage[B_TILE][240]; // per-warp, one stream at a time
    __shared__ float  s_model[B_TILE];

    const int tid = threadIdx.x;
    const int t0  = blockIdx.x * T_TILE;
    const int b0  = blockIdx.y * B_TILE;

    {
        const float* qa[4] = {N, dN, ddN, dddN};
        for (int idx = tid; idx < 4 * KQ * 32; idx += THR) {
            int p = idx / (KQ * 32), r = idx % (KQ * 32);
            int k = r / 32, lt = r % 32;                    // lt fastest -> STS.64 conflict-free
            const float* src = qa[p];
            s_qbp[p][k][lt] = make_float2(src[(t0 + lt) * KQ + k],
                                          src[(t0 + lt + 32) * KQ + k]);
        }
        const float* ta[3] = {Nt, dNt, ddNt};
        for (int idx = tid; idx < 3 * KT * 32; idx += THR) {
            int p = idx / (KT * 32), r = idx % (KT * 32);
            int k = r / 32, lt = r % 32;
            const float* src = ta[p];
            s_tbp[p][k][lt] = make_float2(src[(t0 + lt) * KT + k],
                                          src[(t0 + lt + 32) * KT + k]);
        }
    }
    for (int idx = tid; idx < B_TILE * KQ * NDOF; idx += THR) {
        int w = idx / (KQ * NDOF), r = idx % (KQ * NDOF);
        float c = q_cps[(size_t)b0 * KQ * NDOF + idx];
        u64 p; PACK2(p, c, c);
        s_qcd[w][r / NDOF][r % NDOF] = p;
    }
    for (int idx = tid; idx < B_TILE * KT; idx += THR) {
        float c = t_cps[b0 * KT + idx];
        u64 p; PACK2(p, c, c);
        s_tcd[idx / KT][idx % KT] = p;
    }
    if (tid < 7) {
        s_lims[tid]      = Ldot[tid];
        s_lims[7 + tid]  = Lddot[tid];
        s_lims[14 + tid] = Ldddot[tid];
    }
    __syncthreads();

    const int lane = tid & 31;
    const int w    = tid >> 5;   // local batch 0..7
    const int b    = b0 + w;

    // --- fused time-spline evaluation (packed over the two t-points) ---
    u64 ap = 0, ddp = 0, dddp = 0;
#pragma unroll
    for (int k = 0; k < KT; k++) {
        u64 tc = s_tcd[w][k];                              // broadcast LDS.64
        u64 b0p = *(const u64*)&s_tbp[0][k][lane];
        u64 b1p = *(const u64*)&s_tbp[1][k][lane];
        u64 b2p = *(const u64*)&s_tbp[2][k][lane];
        FMA2(ap,   b0p, tc, ap);
        FMA2(ddp,  b1p, tc, ddp);
        FMA2(dddp, b2p, tc, dddp);
    }
    u64 a2p; MUL2(a2p, ap, ap);
    u64 a3p; MUL2(a3p, a2p, ap);
    u64 c1p; MUL2(c1p, ddp, ap);                            // ddtau * a
    u64 c2p; { u64 t; MUL2(t, ddp, a2p); u64 th; PACK2(th, 3.0f, 3.0f); MUL2(c2p, th, t); }
    u64 c3p; { u64 t; MUL2(t, ddp, ddp); u64 t2; MUL2(t2, t, ap); FMA2(c3p, a2p, dddp, t2); }
    float a0, a1; UNPACK2(a0, a1, ap);
    const float dth[2] = {1.0f / (a0 * (float)NT), 1.0f / (a1 * (float)NT)};

    // --- packed q-spline accumulation over k ---
    u64 q[7]    = {0,0,0,0,0,0,0};
    u64 qd[7]   = {0,0,0,0,0,0,0};
    u64 qdd[7]  = {0,0,0,0,0,0,0};
    u64 qddd[7] = {0,0,0,0,0,0,0};
#pragma unroll
    for (int k = 0; k < KQ; k++) {
        u64 nbx = *(const u64*)&s_qbp[0][k][lane];
        u64 nby = *(const u64*)&s_qbp[1][k][lane];
        u64 nbz = *(const u64*)&s_qbp[2][k][lane];
        u64 nbw = *(const u64*)&s_qbp[3][k][lane];
#pragma unroll
        for (int d = 0; d < 7; d++) {
            u64 cs = s_qcd[w][k][d];  // broadcast LDS.64
            FMA2(q[d],    nbx, cs, q[d]);
            FMA2(qd[d],   nby, cs, qd[d]);
            FMA2(qdd[d],  nbz, cs, qdd[d]);
            FMA2(qddd[d], nbw, cs, qddd[d]);
        }
    }

    float accd[7]   = {0,0,0,0,0,0,0};
    float accdd[7]  = {0,0,0,0,0,0,0};
    float accddd[7] = {0,0,0,0,0,0,0};
    float* st = s_stage[w];

#pragma unroll
    for (int i = 0; i < 2; i++) {
        const float dt = dth[i];
        const size_t chunk = ((size_t)b * NT + t0 + 32 * i) * NDOF; // multiple of 224

        // stream 0: q
#pragma unroll
        for (int d = 0; d < 7; d++) {
            float lo, hi; UNPACK2(lo, hi, q[d]);
            st[1 + 7 * lane + d] = (i == 0) ? lo : hi;     // conflict-free (gcd(7,32)=1)
        }
        __syncwarp();
        flush_chunk(out + OFF_Q + chunk, st, lane);
        __syncwarp();

        // stream 1: q_dot
#pragma unroll
        for (int d = 0; d < 7; d++) {
            u64 v; MUL2(v, qd[d], ap);
            float lo, hi; UNPACK2(lo, hi, v);
            float x = (i == 0) ? lo : hi;
            st[1 + 7 * lane + d] = x;
            accd[d] += huber_relu_dt(x, s_lims[d], dt);
        }
        __syncwarp();
        flush_chunk(out + OFF_QDOT + chunk, st, lane);
        __syncwarp();

        // stream 2: q_ddot
#pragma unroll
        for (int d = 0; d < 7; d++) {
            u64 t1; MUL2(t1, qd[d], c1p);
            u64 v;  FMA2(v, qdd[d], a2p, t1);
            float lo, hi; UNPACK2(lo, hi, v);
            float x = (i == 0) ? lo : hi;
            st[1 + 7 * lane + d] = x;
            accdd[d] += huber_relu_dt(x, s_lims[7 + d], dt);
        }
        __syncwarp();
        flush_chunk(out + OFF_QDDOT + chunk, st, lane);
        __syncwarp();

        // stream 3: q_dddot
#pragma unroll
        for (int d = 0; d < 7; d++) {
            u64 t1; MUL2(t1, qd[d], c3p);
            u64 t2; FMA2(t2, qdd[d], c2p, t1);
            u64 v;  FMA2(v, qddd[d], a3p, t2);
            float lo, hi; UNPACK2(lo, hi, v);
            float x = (i == 0) ? lo : hi;
            st[1 + 7 * lane + d] = x;
            accddd[d] += huber_relu_dt(x, s_lims[14 + d], dt);
        }
        __syncwarp();
        flush_chunk(out + OFF_QDDDOT + chunk, st, lane);
        __syncwarp();
    }

    // warp-reduce the 21 loss accumulators (all lanes same b)
#pragma unroll
    for (int d = 0; d < 7; d++) {
#pragma unroll
        for (int off = 16; off; off >>= 1) {
            accd[d]   += __shfl_xor_sync(0xffffffffu, accd[d],   off);
            accdd[d]  += __shfl_xor_sync(0xffffffffu, accdd[d],  off);
            accddd[d] += __shfl_xor_sync(0xffffffffu, accddd[d], off);
        }
    }
    if (lane == 0) {
        float tot = 0.0f;
#pragma unroll
        for (int d = 0; d < 7; d++) {
            atomicAdd(&out[OFF_QDOT_LOSS   + (size_t)b * NDOF + d], accd[d]);
            atomicAdd(&out[OFF_QDDOT_LOSS  + (size_t)b * NDOF + d], accdd[d]);
            atomicAdd(&out[OFF_QDDDOT_LOSS + (size_t)b * NDOF + d], accddd[d]);
            tot += accd[d] + accdd[d] + accddd[d];
        }
        s_model[w] = tot;
    }
    __syncthreads();
    if (tid == 0) {
        float m = 0.0f;
#pragma unroll
        for (int ww = 0; ww < B_TILE; ww++) m += s_model[ww];
        atomicAdd(&out[OFF_MODEL], m);   // fused finalize
    }
}

// ---------------------------------------------------------------------------
extern "C" void kernel_launch(void* const* d_in, const int* in_sizes, int n_in,
                              void* d_out, int out_size)
{
    const float* q_cps  = (const float*)d_in[0];
    const float* t_cps  = (const float*)d_in[1];
    const float* N      = (const float*)d_in[2];
    const float* dN     = (const float*)d_in[3];
    const float* ddN    = (const float*)d_in[4];
    const float* dddN   = (const float*)d_in[5];
    const float* Nt     = (const float*)d_in[6];
    const float* dNt    = (const float*)d_in[7];
    const float* ddNt   = (const float*)d_in[8];
    const float* Ldot   = (const float*)d_in[9];
    const float* Lddot  = (const float*)d_in[10];
    const float* Ldddot = (const float*)d_in[11];
    // d_in[12] = torque_limits (unused: torque == 0 -> torque_loss == 0)

    float* out = (float*)d_out;

    // zero model_loss + all four loss regions, and the torque output (all zeros)
    cudaMemsetAsync(out, 0, (size_t)OFF_Q * sizeof(float), 0);
    cudaMemsetAsync(out + OFF_TORQUE, 0, QTD * sizeof(float), 0);

    dim3 dgrid(NT / 32, NB / 128);                // (32, 8)
    dt_kernel<<<dgrid, 1024>>>(t_cps, Nt, out);

    cumsum_kernel<<<NB, 1024>>>(out);

    dim3 grid(NT / T_TILE, NB / B_TILE);          // (16, 128)
    main_kernel<<<grid, THR>>>(q_cps, t_cps, N, dN, ddN, dddN,
                               Nt, dNt, ddNt, Ldot, Lddot, Ldddot, out);
}

// round 10
// speedup vs baseline: 1.1045x; 1.0013x over previous
#include <cuda_runtime.h>
#include <cstddef>

typedef unsigned long long u64;

// Problem constants
#define NB   1024
#define NT   1024
#define KQ   15
#define KT   20
#define NDOF 7

// Output layout offsets (fp32 elements), total = 38,827,009
static constexpr size_t OFF_MODEL       = 0;
static constexpr size_t OFF_QDOT_LOSS   = 1;
static constexpr size_t OFF_QDDOT_LOSS  = 1 + 7168;
static constexpr size_t OFF_QDDDOT_LOSS = 1 + 2 * 7168;
static constexpr size_t OFF_TORQUE_LOSS = 1 + 3 * 7168;
static constexpr size_t OFF_Q           = 1 + 4 * 7168;           // 28673 (== 1 mod 4)
static constexpr size_t QTD             = (size_t)NB * NT * NDOF; // 7,340,032
static constexpr size_t OFF_QDOT        = OFF_Q + QTD;
static constexpr size_t OFF_QDDOT       = OFF_Q + 2 * QTD;
static constexpr size_t OFF_QDDDOT      = OFF_Q + 3 * QTD;
static constexpr size_t OFF_TORQUE      = OFF_Q + 4 * QTD;
static constexpr size_t OFF_T           = OFF_Q + 5 * QTD;
static constexpr size_t OFF_TCUM        = OFF_T + NB;
static constexpr size_t OFF_DT          = OFF_TCUM + (size_t)NB * NT;

// ---- packed f32x2 helpers -------------------------------------------------
#define PACK2(out, lo, hi) \
    asm("mov.b64 %0, {%1, %2};" : "=l"(out) : "r"(__float_as_uint(lo)), "r"(__float_as_uint(hi)))
#define UNPACK2(lo, hi, in) do { unsigned int _ulo, _uhi; \
    asm("mov.b64 {%0, %1}, %2;" : "=r"(_ulo), "=r"(_uhi) : "l"(in)); \
    lo = __uint_as_float(_ulo); hi = __uint_as_float(_uhi); } while (0)
#define FMA2(d, a, b, c) asm("fma.rn.f32x2 %0, %1, %2, %3;" : "=l"(d) : "l"(a), "l"(b), "l"(c))
#define MUL2(d, a, b)    asm("mul.rn.f32x2 %0, %1, %2;"     : "=l"(d) : "l"(a), "l"(b))

__device__ __forceinline__ float huber_relu_dt(float v, float lim, float dt) {
    // huber(relu(|v| - lim), delta=1) * dt, branchless
    float r = fmaxf(fabsf(v) - lim, 0.0f);
    float m = fminf(r, 1.0f);
    return (r - 0.5f * m) * m * dt;
}

// ---------------------------------------------------------------------------
// Kernel A: dt stream only. 256-thread blocks for high occupancy.
// Grid (32 t-tiles of 32, 32 b-tiles of 32).
// ---------------------------------------------------------------------------
__global__ __launch_bounds__(256)
void dt_kernel(const float* __restrict__ t_cps,
               const float* __restrict__ Nt,
               float* __restrict__ out)
{
    __shared__ float sNt[KT][32];    // [k][t-local], lt fastest -> conflict-free
    __shared__ float sT[32][21];     // [b-local][k], pad 21

    const int tid = threadIdx.x;
    const int t0  = blockIdx.x * 32;
    const int b0  = blockIdx.y * 32;

    for (int idx = tid; idx < 32 * KT; idx += 256) {
        int k = idx / 32, lt = idx % 32;
        sNt[k][lt] = Nt[(t0 + lt) * KT + k];
    }
    for (int idx = tid; idx < 32 * KT; idx += 256) {
        int bl = idx / KT, k = idx % KT;
        sT[bl][k] = t_cps[(b0 + bl) * KT + k];
    }
    __syncthreads();

    const int tx = tid & 31;
    const int ty = tid >> 5;          // 0..7
#pragma unroll
    for (int j = 0; j < 4; j++) {
        const int bl = ty + 8 * j;    // 0..31
        float a = 0.0f;
#pragma unroll
        for (int k = 0; k < KT; k++)
            a = fmaf(sNt[k][tx], sT[bl][k], a);   // lane-indexed + broadcast
        out[OFF_DT + (size_t)(b0 + bl) * NT + t0 + tx] = 1.0f / (a * (float)NT);
    }
}

// ---------------------------------------------------------------------------
// Kernel B: per-batch inclusive cumsum of dt -> t_cumsum, t. Block = batch.
// ---------------------------------------------------------------------------
__global__ __launch_bounds__(1024)
void cumsum_kernel(float* __restrict__ out)
{
    __shared__ float s_w[32];
    const int t    = threadIdx.x;
    const int lane = t & 31;
    const int wid  = t >> 5;
    const int b    = blockIdx.x;

    float v = out[OFF_DT + (size_t)b * NT + t];
#pragma unroll
    for (int off = 1; off < 32; off <<= 1) {
        float u = __shfl_up_sync(0xffffffffu, v, off);
        if (lane >= off) v += u;
    }
    if (lane == 31) s_w[wid] = v;
    __syncthreads();
    if (wid == 0) {
        float wv = s_w[lane];
#pragma unroll
        for (int off = 1; off < 32; off <<= 1) {
            float u = __shfl_up_sync(0xffffffffu, wv, off);
            if (lane >= off) wv += u;
        }
        s_w[lane] = wv;
    }
    __syncthreads();
    float c = v + (wid > 0 ? s_w[wid - 1] : 0.0f);

    out[OFF_TCUM + (size_t)b * NT + t] = c;
    if (t == NT - 1) out[OFF_T + b] = c;
}

// ---------------------------------------------------------------------------
// Flush a staged 224-float chunk (data at buf[1..224]) to g (g%4 floats == 1):
// 55x STG.128 body + 4 scalar edges.
// ---------------------------------------------------------------------------
__device__ __forceinline__ void flush_chunk(float* __restrict__ g,
                                            const float* __restrict__ buf,
                                            int lane)
{
    float4 x0 = *(const float4*)(buf + 4 * (lane + 1));
    *(float4*)(g + 4 * (lane + 1) - 1) = x0;
    if (lane < 23) {
        float4 x1 = *(const float4*)(buf + 4 * (lane + 33));
        *(float4*)(g + 4 * (lane + 33) - 1) = x1;
    }
    if (lane < 3)       g[lane] = buf[lane + 1];
    else if (lane == 3) g[223]  = buf[224];
}

// ---------------------------------------------------------------------------
// Kernel C: main streaming kernel (packed f32x2 over the two t-points).
// Tile: T_TILE=64 x B_TILE=8 batches, 256 threads (warp = batch).
// Also writes the torque zeros (shared zero buffer) to avoid a serial memset.
// ---------------------------------------------------------------------------
#define T_TILE 64
#define B_TILE 8
#define THR    256

__global__ __launch_bounds__(THR)
void main_kernel(const float* __restrict__ q_cps, const float* __restrict__ t_cps,
                 const float* __restrict__ N,   const float* __restrict__ dN,
                 const float* __restrict__ ddN, const float* __restrict__ dddN,
                 const float* __restrict__ Nt,  const float* __restrict__ dNt,
                 const float* __restrict__ ddNt,
                 const float* __restrict__ Ldot, const float* __restrict__ Lddot,
                 const float* __restrict__ Ldddot,
                 float* __restrict__ out)
{
    __shared__ float2 s_qbp[4][KQ][32];                 // [plane][k][lt-pair]
    __shared__ float2 s_tbp[3][KT][32];                 // time-spline pairs
    __shared__ __align__(16) u64 s_qcd[B_TILE][KQ][8];  // dup q_cps pairs; slot 7 pad
    __shared__ __align__(16) u64 s_tcd[B_TILE][KT];     // dup t_cps pairs
    __shared__ float  s_lims[24];
    __shared__ float  s_stage[B_TILE][4][240];          // per-warp, 4 streams
    __shared__ float  s_zero[240];                      // block-wide zero chunk
    __shared__ float  s_model[B_TILE];

    const int tid = threadIdx.x;
    const int t0  = blockIdx.x * T_TILE;
    const int b0  = blockIdx.y * B_TILE;

    {
        const float* qa[4] = {N, dN, ddN, dddN};
        for (int idx = tid; idx < 4 * KQ * 32; idx += THR) {
            int p = idx / (KQ * 32), r = idx % (KQ * 32);
            int k = r / 32, lt = r % 32;
            const float* src = qa[p];
            s_qbp[p][k][lt] = make_float2(src[(t0 + lt) * KQ + k],
                                          src[(t0 + lt + 32) * KQ + k]);
        }
        const float* ta[3] = {Nt, dNt, ddNt};
        for (int idx = tid; idx < 3 * KT * 32; idx += THR) {
            int p = idx / (KT * 32), r = idx % (KT * 32);
            int k = r / 32, lt = r % 32;
            const float* src = ta[p];
            s_tbp[p][k][lt] = make_float2(src[(t0 + lt) * KT + k],
                                          src[(t0 + lt + 32) * KT + k]);
        }
    }
    for (int idx = tid; idx < B_TILE * KQ * NDOF; idx += THR) {
        int w = idx / (KQ * NDOF), r = idx % (KQ * NDOF);
        float c = q_cps[(size_t)b0 * KQ * NDOF + idx];
        u64 p; PACK2(p, c, c);
        s_qcd[w][r / NDOF][r % NDOF] = p;
    }
    for (int idx = tid; idx < B_TILE * KT; idx += THR) {
        float c = t_cps[b0 * KT + idx];
        u64 p; PACK2(p, c, c);
        s_tcd[idx / KT][idx % KT] = p;
    }
    for (int idx = tid; idx < 240; idx += THR) s_zero[idx] = 0.0f;
    if (tid < 7) {
        s_lims[tid]      = Ldot[tid];
        s_lims[7 + tid]  = Lddot[tid];
        s_lims[14 + tid] = Ldddot[tid];
    }
    __syncthreads();

    const int lane = tid & 31;
    const int w    = tid >> 5;   // local batch 0..7
    const int b    = b0 + w;

    // --- fused time-spline evaluation (packed; k stepped by 2 for LDS.128 cs) ---
    u64 ap = 0, ddp = 0, dddp = 0;
#pragma unroll
    for (int k = 0; k < KT; k += 2) {
        ulonglong2 tc2 = *(const ulonglong2*)&s_tcd[w][k];  // broadcast LDS.128
        FMA2(ap,   *(const u64*)&s_tbp[0][k][lane],     tc2.x, ap);
        FMA2(ddp,  *(const u64*)&s_tbp[1][k][lane],     tc2.x, ddp);
        FMA2(dddp, *(const u64*)&s_tbp[2][k][lane],     tc2.x, dddp);
        FMA2(ap,   *(const u64*)&s_tbp[0][k + 1][lane], tc2.y, ap);
        FMA2(ddp,  *(const u64*)&s_tbp[1][k + 1][lane], tc2.y, ddp);
        FMA2(dddp, *(const u64*)&s_tbp[2][k + 1][lane], tc2.y, dddp);
    }

    // scalar-half time coefficients
    float aS[2], ddS[2], dddS[2];
    UNPACK2(aS[0],   aS[1],   ap);
    UNPACK2(ddS[0],  ddS[1],  ddp);
    UNPACK2(dddS[0], dddS[1], dddp);
    float a2S[2], a3S[2], c1S[2], c2S[2], c3S[2], dtS[2];
#pragma unroll
    for (int h = 0; h < 2; h++) {
        a2S[h] = aS[h] * aS[h];
        a3S[h] = a2S[h] * aS[h];
        c1S[h] = ddS[h] * aS[h];
        c2S[h] = 3.0f * ddS[h] * a2S[h];
        c3S[h] = fmaf(a2S[h], dddS[h], ddS[h] * ddS[h] * aS[h]);
        dtS[h] = 1.0f / (aS[h] * (float)NT);
    }

    // --- packed q-spline accumulation over k ---
    u64 q[7]    = {0,0,0,0,0,0,0};
    u64 qd[7]   = {0,0,0,0,0,0,0};
    u64 qdd[7]  = {0,0,0,0,0,0,0};
    u64 qddd[7] = {0,0,0,0,0,0,0};
#pragma unroll
    for (int k = 0; k < KQ; k++) {
        u64 nbx = *(const u64*)&s_qbp[0][k][lane];
        u64 nby = *(const u64*)&s_qbp[1][k][lane];
        u64 nbz = *(const u64*)&s_qbp[2][k][lane];
        u64 nbw = *(const u64*)&s_qbp[3][k][lane];
        const ulonglong2* csp = (const ulonglong2*)&s_qcd[w][k][0];
        ulonglong2 p01 = csp[0];   // broadcast LDS.128
        ulonglong2 p23 = csp[1];
        ulonglong2 p45 = csp[2];
        ulonglong2 p67 = csp[3];
        u64 cs[7] = {p01.x, p01.y, p23.x, p23.y, p45.x, p45.y, p67.x};
#pragma unroll
        for (int d = 0; d < 7; d++) {
            FMA2(q[d],    nbx, cs[d], q[d]);
            FMA2(qd[d],   nby, cs[d], qd[d]);
            FMA2(qdd[d],  nbz, cs[d], qdd[d]);
            FMA2(qddd[d], nbw, cs[d], qddd[d]);
        }
    }

    float accd[7]   = {0,0,0,0,0,0,0};
    float accdd[7]  = {0,0,0,0,0,0,0};
    float accddd[7] = {0,0,0,0,0,0,0};
    float* st0 = s_stage[w][0];
    float* st1 = s_stage[w][1];
    float* st2 = s_stage[w][2];
    float* st3 = s_stage[w][3];

#pragma unroll
    for (int i = 0; i < 2; i++) {
        const float dt = dtS[i];
#pragma unroll
        for (int d = 0; d < 7; d++) {
            float ql, qh, dl, dh, ddl, ddh, dddl, dddh;
            UNPACK2(ql, qh, q[d]);
            UNPACK2(dl, dh, qd[d]);
            UNPACK2(ddl, ddh, qdd[d]);
            UNPACK2(dddl, dddh, qddd[d]);
            float qv   = (i == 0) ? ql   : qh;
            float qdv  = (i == 0) ? dl   : dh;
            float qddv = (i == 0) ? ddl  : ddh;
            float q3v  = (i == 0) ? dddl : dddh;

            float v1 = qdv * aS[i];
            float v2 = fmaf(qddv, a2S[i], qdv * c1S[i]);
            float v3 = fmaf(q3v, a3S[i], fmaf(qddv, c2S[i], qdv * c3S[i]));

            st0[1 + 7 * lane + d] = qv;   // conflict-free (gcd(7,32)=1)
            st1[1 + 7 * lane + d] = v1;
            st2[1 + 7 * lane + d] = v2;
            st3[1 + 7 * lane + d] = v3;

            accd[d]   += huber_relu_dt(v1, s_lims[d],      dt);
            accdd[d]  += huber_relu_dt(v2, s_lims[7 + d],  dt);
            accddd[d] += huber_relu_dt(v3, s_lims[14 + d], dt);
        }
        __syncwarp();
        const size_t chunk = ((size_t)b * NT + t0 + 32 * i) * NDOF; // multiple of 224
        flush_chunk(out + OFF_Q      + chunk, st0, lane);
        flush_chunk(out + OFF_QDOT   + chunk, st1, lane);
        flush_chunk(out + OFF_QDDOT  + chunk, st2, lane);
        flush_chunk(out + OFF_QDDDOT + chunk, st3, lane);
        flush_chunk(out + OFF_TORQUE + chunk, s_zero, lane);   // torque == 0
        __syncwarp();
    }

    // warp-reduce the 21 loss accumulators (all lanes same b)
#pragma unroll
    for (int d = 0; d < 7; d++) {
#pragma unroll
        for (int off = 16; off; off >>= 1) {
            accd[d]   += __shfl_xor_sync(0xffffffffu, accd[d],   off);
            accdd[d]  += __shfl_xor_sync(0xffffffffu, accdd[d],  off);
            accddd[d] += __shfl_xor_sync(0xffffffffu, accddd[d], off);
        }
    }
    if (lane == 0) {
        float tot = 0.0f;
#pragma unroll
        for (int d = 0; d < 7; d++) {
            atomicAdd(&out[OFF_QDOT_LOSS   + (size_t)b * NDOF + d], accd[d]);
            atomicAdd(&out[OFF_QDDOT_LOSS  + (size_t)b * NDOF + d], accdd[d]);
            atomicAdd(&out[OFF_QDDDOT_LOSS + (size_t)b * NDOF + d], accddd[d]);
            tot += accd[d] + accdd[d] + accddd[d];
        }
        s_model[w] = tot;
    }
    __syncthreads();
    if (tid == 0) {
        float m = 0.0f;
#pragma unroll
        for (int ww = 0; ww < B_TILE; ww++) m += s_model[ww];
        atomicAdd(&out[OFF_MODEL], m);   // fused finalize
    }
}

// ---------------------------------------------------------------------------
extern "C" void kernel_launch(void* const* d_in, const int* in_sizes, int n_in,
                              void* d_out, int out_size)
{
    const float* q_cps  = (const float*)d_in[0];
    const float* t_cps  = (const float*)d_in[1];
    const float* N      = (const float*)d_in[2];
    const float* dN     = (const float*)d_in[3];
    const float* ddN    = (const float*)d_in[4];
    const float* dddN   = (const float*)d_in[5];
    const float* Nt     = (const float*)d_in[6];
    const float* dNt    = (const float*)d_in[7];
    const float* ddNt   = (const float*)d_in[8];
    const float* Ldot   = (const float*)d_in[9];
    const float* Lddot  = (const float*)d_in[10];
    const float* Ldddot = (const float*)d_in[11];
    // d_in[12] = torque_limits (unused: torque == 0 -> torque_loss == 0)

    float* out = (float*)d_out;

    // zero model_loss + all four loss regions (torque output zeros come from main_kernel)
    cudaMemsetAsync(out, 0, (size_t)OFF_Q * sizeof(float), 0);

    dim3 dgrid(NT / 32, NB / 32);                 // (32, 32)
    dt_kernel<<<dgrid, 256>>>(t_cps, Nt, out);

    cumsum_kernel<<<NB, 1024>>>(out);

    dim3 grid(NT / T_TILE, NB / B_TILE);          // (16, 128)
    main_kernel<<<grid, THR>>>(q_cps, t_cps, N, dN, ddN, dddN,
                               Nt, dNt, ddNt, Ldot, Lddot, Ldddot, out);
}

// round 11
// speedup vs baseline: 1.1720x; 1.0611x over previous
#include <cuda_runtime.h>
#include <cstddef>

typedef unsigned long long u64;

// Problem constants
#define NB   1024
#define NT   1024
#define KQ   15
#define KT   20
#define NDOF 7

// Output layout offsets (fp32 elements), total = 38,827,009
static constexpr size_t OFF_MODEL       = 0;
static constexpr size_t OFF_QDOT_LOSS   = 1;
static constexpr size_t OFF_QDDOT_LOSS  = 1 + 7168;
static constexpr size_t OFF_QDDDOT_LOSS = 1 + 2 * 7168;
static constexpr size_t OFF_TORQUE_LOSS = 1 + 3 * 7168;
static constexpr size_t OFF_Q           = 1 + 4 * 7168;           // 28673 (== 1 mod 4)
static constexpr size_t QTD             = (size_t)NB * NT * NDOF; // 7,340,032
static constexpr size_t OFF_QDOT        = OFF_Q + QTD;
static constexpr size_t OFF_QDDOT       = OFF_Q + 2 * QTD;
static constexpr size_t OFF_QDDDOT      = OFF_Q + 3 * QTD;
static constexpr size_t OFF_TORQUE      = OFF_Q + 4 * QTD;
static constexpr size_t OFF_T           = OFF_Q + 5 * QTD;
static constexpr size_t OFF_TCUM        = OFF_T + NB;
static constexpr size_t OFF_DT          = OFF_TCUM + (size_t)NB * NT;

// ---- packed f32x2 helpers -------------------------------------------------
#define PACK2(out, lo, hi) \
    asm("mov.b64 %0, {%1, %2};" : "=l"(out) : "r"(__float_as_uint(lo)), "r"(__float_as_uint(hi)))
#define UNPACK2(lo, hi, in) do { unsigned int _ulo, _uhi; \
    asm("mov.b64 {%0, %1}, %2;" : "=r"(_ulo), "=r"(_uhi) : "l"(in)); \
    lo = __uint_as_float(_ulo); hi = __uint_as_float(_uhi); } while (0)
#define FMA2(d, a, b, c) asm("fma.rn.f32x2 %0, %1, %2, %3;" : "=l"(d) : "l"(a), "l"(b), "l"(c))
#define MUL2(d, a, b)    asm("mul.rn.f32x2 %0, %1, %2;"     : "=l"(d) : "l"(a), "l"(b))

__device__ __forceinline__ float huber_relu_dt(float v, float lim, float dt) {
    // huber(relu(|v| - lim), delta=1) * dt, branchless
    float r = fmaxf(fabsf(v) - lim, 0.0f);
    float m = fminf(r, 1.0f);
    return (r - 0.5f * m) * m * dt;
}

// ---------------------------------------------------------------------------
// Kernel A: dt stream only. 256-thr blocks, grid (32, 32). Coalesced fills
// (Nt/t_cps tile rows are contiguous), conflict-free stride-21 reads.
// ---------------------------------------------------------------------------
__global__ __launch_bounds__(256)
void dt_kernel(const float* __restrict__ t_cps,
               const float* __restrict__ Nt,
               float* __restrict__ out)
{
    __shared__ float sNt[32][21];    // [t-local][k], pad 21
    __shared__ float sT[32][21];     // [b-local][k], pad 21

    const int tid = threadIdx.x;
    const int t0  = blockIdx.x * 32;
    const int b0  = blockIdx.y * 32;

    for (int idx = tid; idx < 32 * KT; idx += 256)
        sNt[idx / KT][idx % KT] = Nt[t0 * KT + idx];        // fully coalesced
    for (int idx = tid; idx < 32 * KT; idx += 256)
        sT[idx / KT][idx % KT] = t_cps[b0 * KT + idx];      // fully coalesced
    __syncthreads();

    const int tx = tid & 31;
    const int ty = tid >> 5;          // 0..7
#pragma unroll
    for (int j = 0; j < 4; j++) {
        const int bl = ty + 8 * j;    // 0..31
        float a = 0.0f;
#pragma unroll
        for (int k = 0; k < KT; k++)
            a = fmaf(sNt[tx][k], sT[bl][k], a);  // stride-21 lane + broadcast: conflict-free
        out[OFF_DT + (size_t)(b0 + bl) * NT + t0 + tx] = 1.0f / (a * (float)NT);
    }
}

// ---------------------------------------------------------------------------
// Kernel B: per-batch inclusive cumsum of dt -> t_cumsum, t. Block = batch.
// ---------------------------------------------------------------------------
__global__ __launch_bounds__(1024)
void cumsum_kernel(float* __restrict__ out)
{
    __shared__ float s_w[32];
    const int t    = threadIdx.x;
    const int lane = t & 31;
    const int wid  = t >> 5;
    const int b    = blockIdx.x;

    float v = out[OFF_DT + (size_t)b * NT + t];
#pragma unroll
    for (int off = 1; off < 32; off <<= 1) {
        float u = __shfl_up_sync(0xffffffffu, v, off);
        if (lane >= off) v += u;
    }
    if (lane == 31) s_w[wid] = v;
    __syncthreads();
    if (wid == 0) {
        float wv = s_w[lane];
#pragma unroll
        for (int off = 1; off < 32; off <<= 1) {
            float u = __shfl_up_sync(0xffffffffu, wv, off);
            if (lane >= off) wv += u;
        }
        s_w[lane] = wv;
    }
    __syncthreads();
    float c = v + (wid > 0 ? s_w[wid - 1] : 0.0f);

    out[OFF_TCUM + (size_t)b * NT + t] = c;
    if (t == NT - 1) out[OFF_T + b] = c;
}

// ---------------------------------------------------------------------------
// Flush a staged 224-float chunk (data at buf[1..224]) to g (g%4 floats == 1):
// 55x STG.128 body + 4 scalar edges.
// ---------------------------------------------------------------------------
__device__ __forceinline__ void flush_chunk(float* __restrict__ g,
                                            const float* __restrict__ buf,
                                            int lane)
{
    float4 x0 = *(const float4*)(buf + 4 * (lane + 1));
    *(float4*)(g + 4 * (lane + 1) - 1) = x0;
    if (lane < 23) {
        float4 x1 = *(const float4*)(buf + 4 * (lane + 33));
        *(float4*)(g + 4 * (lane + 33) - 1) = x1;
    }
    if (lane < 3)       g[lane] = buf[lane + 1];
    else if (lane == 3) g[223]  = buf[224];
}

// ---------------------------------------------------------------------------
// Kernel C: main streaming kernel, sequential folded phases for low regs.
// Tile: T_TILE=64 x B_TILE=8 batches, 256 threads (warp = batch).
// Streams processed qd -> qdd -> qddd -> q; losses accumulated from the
// staged buffers by 28 lanes into 3 registers.
// ---------------------------------------------------------------------------
#define T_TILE 64
#define B_TILE 8
#define THR    256

__global__ __launch_bounds__(THR, 3)
void main_kernel(const float* __restrict__ q_cps, const float* __restrict__ t_cps,
                 const float* __restrict__ N,   const float* __restrict__ dN,
                 const float* __restrict__ ddN, const float* __restrict__ dddN,
                 const float* __restrict__ Nt,  const float* __restrict__ dNt,
                 const float* __restrict__ ddNt,
                 const float* __restrict__ Ldot, const float* __restrict__ Lddot,
                 const float* __restrict__ Ldddot,
                 float* __restrict__ out)
{
    __shared__ float2 s_qbp[4][KQ][32];                 // [plane][k][lt-pair]
    __shared__ float2 s_tbp[3][KT][32];                 // time-spline pairs
    __shared__ __align__(16) u64 s_qcd[B_TILE][KQ][8];  // dup q_cps pairs; slot 7 pad
    __shared__ __align__(16) u64 s_tcd[B_TILE][KT];     // dup t_cps pairs
    __shared__ float  s_lims[24];
    __shared__ float  s_stage[B_TILE][2][240];          // per-warp, i=0 / i=1
    __shared__ float  s_dt[B_TILE][64];                 // per-warp dt per t
    __shared__ float  s_zero[240];                      // block-wide zero chunk
    __shared__ float  s_model[B_TILE];

    const int tid = threadIdx.x;
    const int t0  = blockIdx.x * T_TILE;
    const int b0  = blockIdx.y * B_TILE;

    {
        const float* qa[4] = {N, dN, ddN, dddN};
        for (int idx = tid; idx < 4 * KQ * 32; idx += THR) {
            int p = idx / (KQ * 32), r = idx % (KQ * 32);
            int k = r / 32, lt = r % 32;
            const float* src = qa[p];
            s_qbp[p][k][lt] = make_float2(src[(t0 + lt) * KQ + k],
                                          src[(t0 + lt + 32) * KQ + k]);
        }
        const float* ta[3] = {Nt, dNt, ddNt};
        for (int idx = tid; idx < 3 * KT * 32; idx += THR) {
            int p = idx / (KT * 32), r = idx % (KT * 32);
            int k = r / 32, lt = r % 32;
            const float* src = ta[p];
            s_tbp[p][k][lt] = make_float2(src[(t0 + lt) * KT + k],
                                          src[(t0 + lt + 32) * KT + k]);
        }
    }
    for (int idx = tid; idx < B_TILE * KQ * NDOF; idx += THR) {
        int w = idx / (KQ * NDOF), r = idx % (KQ * NDOF);
        float c = q_cps[(size_t)b0 * KQ * NDOF + idx];
        u64 p; PACK2(p, c, c);
        s_qcd[w][r / NDOF][r % NDOF] = p;
    }
    for (int idx = tid; idx < B_TILE * KT; idx += THR) {
        float c = t_cps[b0 * KT + idx];
        u64 p; PACK2(p, c, c);
        s_tcd[idx / KT][idx % KT] = p;
    }
    for (int idx = tid; idx < 240; idx += THR) s_zero[idx] = 0.0f;
    if (tid < 7) {
        s_lims[tid]      = Ldot[tid];
        s_lims[7 + tid]  = Lddot[tid];
        s_lims[14 + tid] = Ldddot[tid];
    }
    __syncthreads();

    const int lane = tid & 31;
    const int w    = tid >> 5;   // local batch 0..7
    const int b    = b0 + w;

    // --- fused time-spline evaluation (packed) ---
    u64 ap = 0, ddp = 0, dddp = 0;
#pragma unroll
    for (int k = 0; k < KT; k += 2) {
        ulonglong2 tc2 = *(const ulonglong2*)&s_tcd[w][k];  // broadcast LDS.128
        FMA2(ap,   *(const u64*)&s_tbp[0][k][lane],     tc2.x, ap);
        FMA2(ddp,  *(const u64*)&s_tbp[1][k][lane],     tc2.x, ddp);
        FMA2(dddp, *(const u64*)&s_tbp[2][k][lane],     tc2.x, dddp);
        FMA2(ap,   *(const u64*)&s_tbp[0][k + 1][lane], tc2.y, ap);
        FMA2(ddp,  *(const u64*)&s_tbp[1][k + 1][lane], tc2.y, ddp);
        FMA2(dddp, *(const u64*)&s_tbp[2][k + 1][lane], tc2.y, dddp);
    }
    // packed coefficients (ddp/dddp die here)
    u64 a2p; MUL2(a2p, ap, ap);
    u64 a3p; MUL2(a3p, a2p, ap);
    u64 c1p; MUL2(c1p, ddp, ap);
    u64 c2p; { u64 t; MUL2(t, ddp, a2p); u64 th; PACK2(th, 3.0f, 3.0f); MUL2(c2p, th, t); }
    u64 c3p; { u64 t; MUL2(t, ddp, ddp); u64 t2; MUL2(t2, t, ap); FMA2(c3p, a2p, dddp, t2); }
    {
        float a0, a1; UNPACK2(a0, a1, ap);
        s_dt[w][lane]      = 1.0f / (a0 * (float)NT);
        s_dt[w][32 + lane] = 1.0f / (a1 * (float)NT);
    }

    // per-lane loss constants (lanes 0..27: d = lane>>2, g = lane&3)
    const int ld = lane >> 2;
    const int lg = lane & 3;
    float limA = 0.f, limB = 0.f, limC = 0.f;
    if (lane < 28) { limA = s_lims[ld]; limB = s_lims[7 + ld]; limC = s_lims[14 + ld]; }
    float acc1 = 0.f, acc2 = 0.f, acc3 = 0.f;

    float* sa = s_stage[w][0];
    float* sb = s_stage[w][1];
    const float* sdt = s_dt[w];
    const size_t chunk0 = ((size_t)b * NT + t0) * NDOF;       // multiple of 224
    const size_t chunk1 = chunk0 + 224;

    u64 accP[7];   // phase accumulator
    u64 u[7];      // qd*c1 (for v2)

    // ======== Phase A: qd -> v1; fold u = qd*c1, accP <- qd*c3 ========
#pragma unroll
    for (int d = 0; d < 7; d++) accP[d] = 0;
#pragma unroll
    for (int k = 0; k < KQ; k++) {
        u64 nb = *(const u64*)&s_qbp[1][k][lane];
        const ulonglong2* csp = (const ulonglong2*)&s_qcd[w][k][0];
        ulonglong2 p01 = csp[0], p23 = csp[1], p45 = csp[2], p67 = csp[3];
        u64 cs[7] = {p01.x, p01.y, p23.x, p23.y, p45.x, p45.y, p67.x};
#pragma unroll
        for (int d = 0; d < 7; d++) FMA2(accP[d], nb, cs[d], accP[d]);
    }
    __syncwarp();
#pragma unroll
    for (int d = 0; d < 7; d++) {
        u64 v; MUL2(v, accP[d], ap);
        float lo, hi; UNPACK2(lo, hi, v);
        sa[1 + 7 * lane + d] = lo;
        sb[1 + 7 * lane + d] = hi;
        MUL2(u[d], accP[d], c1p);
        MUL2(accP[d], accP[d], c3p);   // accP becomes vv = qd*c3
    }
    __syncwarp();
    flush_chunk(out + OFF_QDOT + chunk0, sa, lane);
    flush_chunk(out + OFF_QDOT + chunk1, sb, lane);
    if (lane < 28) {
#pragma unroll
        for (int j = 0; j < 8; j++) {
            int t8 = 8 * lg + j;
            acc1 += huber_relu_dt(sa[1 + 7 * t8 + ld], limA, sdt[t8]);
            acc1 += huber_relu_dt(sb[1 + 7 * t8 + ld], limA, sdt[32 + t8]);
        }
    }

    // ======== Phase B: qdd -> v2 = qdd*a2 + u; fold accP <- qdd*c2 + vv ========
    {
        u64 s2[7];
#pragma unroll
        for (int d = 0; d < 7; d++) s2[d] = 0;
#pragma unroll
        for (int k = 0; k < KQ; k++) {
            u64 nb = *(const u64*)&s_qbp[2][k][lane];
            const ulonglong2* csp = (const ulonglong2*)&s_qcd[w][k][0];
            ulonglong2 p01 = csp[0], p23 = csp[1], p45 = csp[2], p67 = csp[3];
            u64 cs[7] = {p01.x, p01.y, p23.x, p23.y, p45.x, p45.y, p67.x};
#pragma unroll
            for (int d = 0; d < 7; d++) FMA2(s2[d], nb, cs[d], s2[d]);
        }
        __syncwarp();
#pragma unroll
        for (int d = 0; d < 7; d++) {
            u64 v; FMA2(v, s2[d], a2p, u[d]);
            float lo, hi; UNPACK2(lo, hi, v);
            sa[1 + 7 * lane + d] = lo;
            sb[1 + 7 * lane + d] = hi;
            FMA2(accP[d], s2[d], c2p, accP[d]);   // accP becomes w = qdd*c2 + vv
        }
        __syncwarp();
        flush_chunk(out + OFF_QDDOT + chunk0, sa, lane);
        flush_chunk(out + OFF_QDDOT + chunk1, sb, lane);
        if (lane < 28) {
#pragma unroll
            for (int j = 0; j < 8; j++) {
                int t8 = 8 * lg + j;
                acc2 += huber_relu_dt(sa[1 + 7 * t8 + ld], limB, sdt[t8]);
                acc2 += huber_relu_dt(sb[1 + 7 * t8 + ld], limB, sdt[32 + t8]);
            }
        }
    }

    // ======== Phase C: qddd -> v3 = qddd*a3 + w; torque zeros ========
    {
        u64 s3[7];
#pragma unroll
        for (int d = 0; d < 7; d++) s3[d] = 0;
#pragma unroll
        for (int k = 0; k < KQ; k++) {
            u64 nb = *(const u64*)&s_qbp[3][k][lane];
            const ulonglong2* csp = (const ulonglong2*)&s_qcd[w][k][0];
            ulonglong2 p01 = csp[0], p23 = csp[1], p45 = csp[2], p67 = csp[3];
            u64 cs[7] = {p01.x, p01.y, p23.x, p23.y, p45.x, p45.y, p67.x};
#pragma unroll
            for (int d = 0; d < 7; d++) FMA2(s3[d], nb, cs[d], s3[d]);
        }
        __syncwarp();
#pragma unroll
        for (int d = 0; d < 7; d++) {
            u64 v; FMA2(v, s3[d], a3p, accP[d]);
            float lo, hi; UNPACK2(lo, hi, v);
            sa[1 + 7 * lane + d] = lo;
            sb[1 + 7 * lane + d] = hi;
        }
        __syncwarp();
        flush_chunk(out + OFF_QDDDOT + chunk0, sa, lane);
        flush_chunk(out + OFF_QDDDOT + chunk1, sb, lane);
        flush_chunk(out + OFF_TORQUE + chunk0, s_zero, lane);
        flush_chunk(out + OFF_TORQUE + chunk1, s_zero, lane);
        if (lane < 28) {
#pragma unroll
            for (int j = 0; j < 8; j++) {
                int t8 = 8 * lg + j;
                acc3 += huber_relu_dt(sa[1 + 7 * t8 + ld], limC, sdt[t8]);
                acc3 += huber_relu_dt(sb[1 + 7 * t8 + ld], limC, sdt[32 + t8]);
            }
        }
    }

    // ======== Phase D: q (no loss) ========
    {
#pragma unroll
        for (int d = 0; d < 7; d++) accP[d] = 0;
#pragma unroll
        for (int k = 0; k < KQ; k++) {
            u64 nb = *(const u64*)&s_qbp[0][k][lane];
            const ulonglong2* csp = (const ulonglong2*)&s_qcd[w][k][0];
            ulonglong2 p01 = csp[0], p23 = csp[1], p45 = csp[2], p67 = csp[3];
            u64 cs[7] = {p01.x, p01.y, p23.x, p23.y, p45.x, p45.y, p67.x};
#pragma unroll
            for (int d = 0; d < 7; d++) FMA2(accP[d], nb, cs[d], accP[d]);
        }
        __syncwarp();
#pragma unroll
        for (int d = 0; d < 7; d++) {
            float lo, hi; UNPACK2(lo, hi, accP[d]);
            sa[1 + 7 * lane + d] = lo;
            sb[1 + 7 * lane + d] = hi;
        }
        __syncwarp();
        flush_chunk(out + OFF_Q + chunk0, sa, lane);
        flush_chunk(out + OFF_Q + chunk1, sb, lane);
    }

    // ======== loss reduction: 4-lane groups per dof ========
    acc1 += __shfl_xor_sync(0xffffffffu, acc1, 1);
    acc1 += __shfl_xor_sync(0xffffffffu, acc1, 2);
    acc2 += __shfl_xor_sync(0xffffffffu, acc2, 1);
    acc2 += __shfl_xor_sync(0xffffffffu, acc2, 2);
    acc3 += __shfl_xor_sync(0xffffffffu, acc3, 1);
    acc3 += __shfl_xor_sync(0xffffffffu, acc3, 2);

    float tsum = 0.f;
    if (lane < 28 && (lane & 3) == 0) {
        atomicAdd(&out[OFF_QDOT_LOSS   + (size_t)b * NDOF + ld], acc1);
        atomicAdd(&out[OFF_QDDOT_LOSS  + (size_t)b * NDOF + ld], acc2);
        atomicAdd(&out[OFF_QDDDOT_LOSS + (size_t)b * NDOF + ld], acc3);
        tsum = acc1 + acc2 + acc3;
    }
    tsum += __shfl_xor_sync(0xffffffffu, tsum, 4);
    tsum += __shfl_xor_sync(0xffffffffu, tsum, 8);
    tsum += __shfl_xor_sync(0xffffffffu, tsum, 16);
    if (lane == 0) s_model[w] = tsum;
    __syncthreads();
    if (tid == 0) {
        float m = 0.0f;
#pragma unroll
        for (int ww = 0; ww < B_TILE; ww++) m += s_model[ww];
        atomicAdd(&out[OFF_MODEL], m);   // fused finalize
    }
}

// ---------------------------------------------------------------------------
extern "C" void kernel_launch(void* const* d_in, const int* in_sizes, int n_in,
                              void* d_out, int out_size)
{
    const float* q_cps  = (const float*)d_in[0];
    const float* t_cps  = (const float*)d_in[1];
    const float* N      = (const float*)d_in[2];
    const float* dN     = (const float*)d_in[3];
    const float* ddN    = (const float*)d_in[4];
    const float* dddN   = (const float*)d_in[5];
    const float* Nt     = (const float*)d_in[6];
    const float* dNt    = (const float*)d_in[7];
    const float* ddNt   = (const float*)d_in[8];
    const float* Ldot   = (const float*)d_in[9];
    const float* Lddot  = (const float*)d_in[10];
    const float* Ldddot = (const float*)d_in[11];
    // d_in[12] = torque_limits (unused: torque == 0 -> torque_loss == 0)

    float* out = (float*)d_out;

    // zero model_loss + all four loss regions (torque output zeros come from main_kernel)
    cudaMemsetAsync(out, 0, (size_t)OFF_Q * sizeof(float), 0);

    dim3 dgrid(NT / 32, NB / 32);                 // (32, 32)
    dt_kernel<<<dgrid, 256>>>(t_cps, Nt, out);

    cumsum_kernel<<<NB, 1024>>>(out);

    dim3 grid(NT / T_TILE, NB / B_TILE);          // (16, 128)
    main_kernel<<<grid, THR>>>(q_cps, t_cps, N, dN, ddN, dddN,
                               Nt, dNt, ddNt, Ldot, Lddot, Ldddot, out);
}